// round 4
// baseline (speedup 1.0000x reference)
#include <cuda_runtime.h>

#define BB 8
#define PP 12000
#define NP (BB*PP)
#define XN_ 144
#define CELLS (144*144)

// per-(batch,cell) winning pillar index (last write wins == max p)
__device__ int g_winner[BB * CELLS];

__global__ void k_winner(const int* __restrict__ idx) {
    int i = blockIdx.x * blockDim.x + threadIdx.x;
    if (i >= NP) return;
    int y = idx[i * 3 + 1];
    int x = idx[i * 3 + 2];
    x = min(max(x, 0), 143);
    y = min(max(y, 0), 143);
    int b = i / PP;
    int p = i - b * PP;
    atomicMax(&g_winner[b * CELLS + y * XN_ + x], p);
}

__device__ __forceinline__ unsigned long long fma2(unsigned long long a,
                                                   unsigned long long b,
                                                   unsigned long long c) {
    unsigned long long d;
    asm("fma.rn.f32x2 %0, %1, %2, %3;" : "=l"(d) : "l"(a), "l"(b), "l"(c));
    return d;
}
__device__ __forceinline__ unsigned long long splat2(float s) {
    unsigned long long d;
    asm("mov.b64 %0, {%1, %1};" : "=l"(d) : "f"(s));
    return d;
}
__device__ __forceinline__ unsigned long long pack2(float lo, float hi) {
    unsigned long long d;
    asm("mov.b64 %0, {%1, %2};" : "=l"(d) : "f"(lo), "f"(hi));
    return d;
}
__device__ __forceinline__ void unpack2(unsigned long long v, float& lo, float& hi) {
    asm("mov.b64 {%0, %1}, %2;" : "=f"(lo), "=f"(hi) : "l"(v));
}

// Persistent kernel. One warp per pillar (grid-stride).
// Lane = (cg, mg): cg = lane>>2 owns 8 channels [8cg, 8cg+8);
//                  mg = lane&3  owns 8 m-points [8mg, 8mg+8).
// Weights (8ch x 9f, packed f32x2 over channel pairs) + BN constants live in
// registers for the whole kernel. Pillar copied raw into smem (coalesced,
// conflict-free); x read as scalar LDS.32 (4 distinct addrs, broadcast, 1 wf).
__global__ void __launch_bounds__(256, 2) k_compute(
    const float* __restrict__ pillars,
    const int* __restrict__ idx,
    const float* __restrict__ cw,
    const float* __restrict__ gamma,
    const float* __restrict__ beta,
    const float* __restrict__ mean,
    const float* __restrict__ var,
    float* __restrict__ out)
{
    __shared__ __align__(16) float sm[8][288];
    const int wlocal = threadIdx.x >> 5;
    const int lane   = threadIdx.x & 31;
    const int cg     = lane >> 2;       // channel group: channels 8cg..8cg+7
    const int mg     = lane & 3;        // m group: m = 8mg..8mg+7
    float* smp = sm[wlocal];

    // Per-warp constants (loaded once): w packed over channel pairs.
    // wp[f][cp] = (w[8cg+2cp][f], w[8cg+2cp+1][f])
    unsigned long long wp[9][4];
    #pragma unroll
    for (int cp = 0; cp < 4; cp++) {
        const float* w0 = cw + (cg * 8 + 2 * cp) * 9;
        #pragma unroll
        for (int f = 0; f < 9; f++)
            wp[f][cp] = pack2(w0[f], w0[9 + f]);
    }
    // BN constants for the 2 channels this lane will store: c = 8cg + 2mg + {0,1}
    const int cs = cg * 8 + mg * 2;
    const float s0 = gamma[cs]     * rsqrtf(var[cs]     + 1e-5f);
    const float s1 = gamma[cs + 1] * rsqrtf(var[cs + 1] + 1e-5f);
    const float b0 = beta[cs]     - mean[cs]     * s0;
    const float b1 = beta[cs + 1] - mean[cs + 1] * s1;

    const int totalWarps = (gridDim.x * blockDim.x) >> 5;
    const int w0id = (blockIdx.x * blockDim.x + threadIdx.x) >> 5;

    for (int u = w0id; u < NP; u += totalWarps) {
        int y  = idx[u * 3 + 1];
        int xx = idx[u * 3 + 2];
        xx = min(max(xx, 0), 143);
        y  = min(max(y, 0), 143);
        const int b = u / PP;
        const int p = u - b * PP;
        const int flat = y * XN_ + xx;
        if (g_winner[b * CELLS + flat] != p) continue;   // loser: skip all work

        // Raw coalesced copy of the 288-float pillar (no transpose needed)
        const float* src = pillars + (size_t)u * 288;
        #pragma unroll
        for (int k = 0; k < 9; k++)
            smp[lane + k * 32] = src[lane + k * 32];
        __syncwarp();

        // 8 running channel maxes (scalar)
        float mx[8];
        #pragma unroll
        for (int j = 0; j < 8; j++) mx[j] = -3.402823466e38f;

        #pragma unroll
        for (int mi = 0; mi < 8; mi++) {
            const float* xr = smp + (mg * 8 + mi) * 9;
            unsigned long long a0 = 0ull, a1 = 0ull, a2 = 0ull, a3 = 0ull;
            #pragma unroll
            for (int f = 0; f < 9; f++) {
                unsigned long long xs = splat2(xr[f]);
                a0 = fma2(xs, wp[f][0], a0);
                a1 = fma2(xs, wp[f][1], a1);
                a2 = fma2(xs, wp[f][2], a2);
                a3 = fma2(xs, wp[f][3], a3);
            }
            float t0, t1;
            unpack2(a0, t0, t1); mx[0] = fmaxf(mx[0], t0); mx[1] = fmaxf(mx[1], t1);
            unpack2(a1, t0, t1); mx[2] = fmaxf(mx[2], t0); mx[3] = fmaxf(mx[3], t1);
            unpack2(a2, t0, t1); mx[4] = fmaxf(mx[4], t0); mx[5] = fmaxf(mx[5], t1);
            unpack2(a3, t0, t1); mx[6] = fmaxf(mx[6], t0); mx[7] = fmaxf(mx[7], t1);
        }
        __syncwarp();   // smem free for next pillar

        // Reduce max over the 4 mg lanes (lane = cg*4 + mg: xor 1, then 2)
        #pragma unroll
        for (int j = 0; j < 8; j++) {
            mx[j] = fmaxf(mx[j], __shfl_xor_sync(0xFFFFFFFFu, mx[j], 1));
            mx[j] = fmaxf(mx[j], __shfl_xor_sync(0xFFFFFFFFu, mx[j], 2));
        }

        // This lane finalizes channels cs, cs+1 (BN+ReLU after max: exact fold)
        const float fA = fmaxf(fmaf(mx[mg * 2],     s0, b0), 0.0f);
        const float fB = fmaxf(fmaf(mx[mg * 2 + 1], s1, b1), 0.0f);

        const size_t base = ((size_t)(b * 64 + cs)) * CELLS + flat;
        out[base]         = fA;
        out[base + CELLS] = fB;
    }
}

extern "C" void kernel_launch(void* const* d_in, const int* in_sizes, int n_in,
                              void* d_out, int out_size) {
    const float* pillars = (const float*)d_in[0];
    const int*   idx     = (const int*)d_in[1];
    const float* cw      = (const float*)d_in[2];
    const float* gamma   = (const float*)d_in[3];
    const float* beta    = (const float*)d_in[4];
    const float* mean    = (const float*)d_in[5];
    const float* var     = (const float*)d_in[6];
    float* out = (float*)d_out;

    void* winner_ptr = nullptr;
    cudaGetSymbolAddress(&winner_ptr, g_winner);

    cudaMemsetAsync(out, 0, (size_t)out_size * sizeof(float), 0);
    cudaMemsetAsync(winner_ptr, 0xFF, sizeof(int) * BB * CELLS, 0);  // -1
    k_winner<<<(NP + 255) / 256, 256>>>(idx);
    k_compute<<<304, 256>>>(pillars, idx, cw, gamma, beta, mean, var, out);
}

// round 5
// speedup vs baseline: 1.0900x; 1.0900x over previous
#include <cuda_runtime.h>

#define BB 8
#define PP 12000
#define NP (BB*PP)
#define XN_ 144
#define CELLS (144*144)
#define NBLK 304
#define NWARPS (NBLK*8)

// per-(batch,cell) winning pillar index (last write wins == max p)
__device__ int  g_winner[BB * CELLS];
__device__ int  g_count;
__device__ int2 g_list[NP];      // (pillar id, out-base = b*64*CELLS + flat)

__global__ void k_winner(const int* __restrict__ idx) {
    int i = blockIdx.x * blockDim.x + threadIdx.x;   // grid sized exactly NP
    int y = idx[i * 3 + 1];
    int x = idx[i * 3 + 2];
    x = min(max(x, 0), 143);
    y = min(max(y, 0), 143);
    int b = i / PP;
    int p = i - b * PP;
    atomicMax(&g_winner[b * CELLS + y * XN_ + x], p);
}

// Compact winners into g_list (warp-aggregated atomic: 1 atomicAdd per warp).
__global__ void k_collect(const int* __restrict__ idx) {
    int i = blockIdx.x * blockDim.x + threadIdx.x;
    int lane = threadIdx.x & 31;
    int y = idx[i * 3 + 1];
    int x = idx[i * 3 + 2];
    x = min(max(x, 0), 143);
    y = min(max(y, 0), 143);
    int b = i / PP;
    int p = i - b * PP;
    int flat = y * XN_ + x;
    bool win = (g_winner[b * CELLS + flat] == p);
    unsigned m = __ballot_sync(0xFFFFFFFFu, win);
    int base = 0;
    if (lane == 0 && m) base = atomicAdd(&g_count, __popc(m));
    base = __shfl_sync(0xFFFFFFFFu, base, 0);
    if (win) {
        int pos = base + __popc(m & ((1u << lane) - 1u));
        g_list[pos] = make_int2(i, b * 64 * CELLS + flat);
    }
}

__device__ __forceinline__ unsigned long long fma2(unsigned long long a,
                                                   unsigned long long b,
                                                   unsigned long long c) {
    unsigned long long d;
    asm("fma.rn.f32x2 %0, %1, %2, %3;" : "=l"(d) : "l"(a), "l"(b), "l"(c));
    return d;
}
__device__ __forceinline__ unsigned long long splat2(float s) {
    unsigned long long d;
    asm("mov.b64 %0, {%1, %1};" : "=l"(d) : "f"(s));
    return d;
}
__device__ __forceinline__ unsigned long long pack2(float lo, float hi) {
    unsigned long long d;
    asm("mov.b64 %0, {%1, %2};" : "=l"(d) : "f"(lo), "f"(hi));
    return d;
}
__device__ __forceinline__ void unpack2(unsigned long long v, float& lo, float& hi) {
    asm("mov.b64 {%0, %1}, %2;" : "=f"(lo), "=f"(hi) : "l"(v));
}
__device__ __forceinline__ unsigned smaddr(const void* p) {
    unsigned r;
    asm("{ .reg .u64 t; cvta.to.shared.u64 t, %1; cvt.u32.u64 %0, t; }"
        : "=r"(r) : "l"(p));
    return r;
}
// Copy one 1152-byte pillar global->shared via cp.async (72 x 16B chunks).
__device__ __forceinline__ void cp_pillar(unsigned sbase, const float* g, int lane) {
    asm volatile("cp.async.cg.shared.global [%0], [%1], 16;"
                 :: "r"(sbase + lane * 16), "l"(g + lane * 4));
    asm volatile("cp.async.cg.shared.global [%0], [%1], 16;"
                 :: "r"(sbase + (lane + 32) * 16), "l"(g + (lane + 32) * 4));
    if (lane < 8)
        asm volatile("cp.async.cg.shared.global [%0], [%1], 16;"
                     :: "r"(sbase + (lane + 64) * 16), "l"(g + (lane + 64) * 4));
}

// Persistent kernel over the compacted winner list. One warp per winner.
// Lane = (cg, mg): cg = lane>>2 owns channels [8cg, 8cg+8),
//                  mg = lane&3  owns m-points  [8mg, 8mg+8).
// Pillar data double-buffered in smem via cp.async, prefetched 1 iter ahead;
// list entries prefetched 2 iters ahead.
__global__ void __launch_bounds__(256, 2) k_compute(
    const float* __restrict__ pillars,
    const float* __restrict__ cw,
    const float* __restrict__ gamma,
    const float* __restrict__ beta,
    const float* __restrict__ mean,
    const float* __restrict__ var,
    float* __restrict__ out)
{
    __shared__ __align__(16) float sm[8][2][288];
    const int wlocal = threadIdx.x >> 5;
    const int lane   = threadIdx.x & 31;
    const int cg     = lane >> 2;
    const int mg     = lane & 3;

    // Per-warp constants (loaded once): wp[f][cp] = (w[8cg+2cp][f], w[8cg+2cp+1][f])
    unsigned long long wp[9][4];
    #pragma unroll
    for (int cp = 0; cp < 4; cp++) {
        const float* w0 = cw + (cg * 8 + 2 * cp) * 9;
        #pragma unroll
        for (int f = 0; f < 9; f++)
            wp[f][cp] = pack2(w0[f], w0[9 + f]);
    }
    const int cs = cg * 8 + mg * 2;   // channels this lane stores
    const float s0 = gamma[cs]     * rsqrtf(var[cs]     + 1e-5f);
    const float s1 = gamma[cs + 1] * rsqrtf(var[cs + 1] + 1e-5f);
    const float b0 = beta[cs]     - mean[cs]     * s0;
    const float b1 = beta[cs + 1] - mean[cs + 1] * s1;

    const int count = g_count;
    const int w0id  = (blockIdx.x * blockDim.x + threadIdx.x) >> 5;

    unsigned sbuf0 = smaddr(&sm[wlocal][0][0]);
    unsigned sbuf1 = smaddr(&sm[wlocal][1][0]);

    int i = w0id;
    int2 eA = g_list[(i < count) ? i : 0];
    int2 eB = g_list[(i + NWARPS < count) ? i + NWARPS : 0];
    if (i < count)
        cp_pillar(sbuf0, pillars + (size_t)eA.x * 288, lane);
    asm volatile("cp.async.commit_group;");
    int p = 0;

    for (; i < count; i += NWARPS) {
        // prefetch list entry 2 ahead
        int i2 = i + 2 * NWARPS;
        int2 eC = g_list[(i2 < count) ? i2 : 0];
        // prefetch next pillar into the other buffer
        if (i + NWARPS < count)
            cp_pillar(p ? sbuf0 : sbuf1, pillars + (size_t)eB.x * 288, lane);
        asm volatile("cp.async.commit_group;");
        asm volatile("cp.async.wait_group 1;");   // current buffer ready
        __syncwarp();

        const float* buf = &sm[wlocal][p][0];
        float mx[8];
        #pragma unroll
        for (int j = 0; j < 8; j++) mx[j] = -3.402823466e38f;

        #pragma unroll
        for (int mi = 0; mi < 8; mi++) {
            const float* xr = buf + (mg * 8 + mi) * 9;
            unsigned long long a0 = 0ull, a1 = 0ull, a2 = 0ull, a3 = 0ull;
            #pragma unroll
            for (int f = 0; f < 9; f++) {
                unsigned long long xs = splat2(xr[f]);
                a0 = fma2(xs, wp[f][0], a0);
                a1 = fma2(xs, wp[f][1], a1);
                a2 = fma2(xs, wp[f][2], a2);
                a3 = fma2(xs, wp[f][3], a3);
            }
            float t0, t1;
            unpack2(a0, t0, t1); mx[0] = fmaxf(mx[0], t0); mx[1] = fmaxf(mx[1], t1);
            unpack2(a1, t0, t1); mx[2] = fmaxf(mx[2], t0); mx[3] = fmaxf(mx[3], t1);
            unpack2(a2, t0, t1); mx[4] = fmaxf(mx[4], t0); mx[5] = fmaxf(mx[5], t1);
            unpack2(a3, t0, t1); mx[6] = fmaxf(mx[6], t0); mx[7] = fmaxf(mx[7], t1);
        }
        __syncwarp();   // all lanes done reading buf before it is refilled

        // Reduce max over the 4 mg lanes (lane = cg*4 + mg)
        #pragma unroll
        for (int j = 0; j < 8; j++) {
            mx[j] = fmaxf(mx[j], __shfl_xor_sync(0xFFFFFFFFu, mx[j], 1));
            mx[j] = fmaxf(mx[j], __shfl_xor_sync(0xFFFFFFFFu, mx[j], 2));
        }

        // BN+ReLU applied once to the raw max (scale>0, monotone => exact)
        const float fA = fmaxf(fmaf(mx[mg * 2],     s0, b0), 0.0f);
        const float fB = fmaxf(fmaf(mx[mg * 2 + 1], s1, b1), 0.0f);
        const size_t base = (size_t)eA.y + (size_t)cs * CELLS;
        out[base]         = fA;
        out[base + CELLS] = fB;

        eA = eB; eB = eC; p ^= 1;
    }
}

extern "C" void kernel_launch(void* const* d_in, const int* in_sizes, int n_in,
                              void* d_out, int out_size) {
    const float* pillars = (const float*)d_in[0];
    const int*   idx     = (const int*)d_in[1];
    const float* cw      = (const float*)d_in[2];
    const float* gamma   = (const float*)d_in[3];
    const float* beta    = (const float*)d_in[4];
    const float* mean    = (const float*)d_in[5];
    const float* var     = (const float*)d_in[6];
    float* out = (float*)d_out;

    void *winner_ptr = nullptr, *count_ptr = nullptr;
    cudaGetSymbolAddress(&winner_ptr, g_winner);
    cudaGetSymbolAddress(&count_ptr, g_count);

    cudaMemsetAsync(out, 0, (size_t)out_size * sizeof(float), 0);
    cudaMemsetAsync(winner_ptr, 0xFF, sizeof(int) * BB * CELLS, 0);  // -1
    cudaMemsetAsync(count_ptr, 0, sizeof(int), 0);
    k_winner<<<NP / 256, 256>>>(idx);
    k_collect<<<NP / 256, 256>>>(idx);
    k_compute<<<NBLK, 256>>>(pillars, cw, gamma, beta, mean, var, out);
}

// round 6
// speedup vs baseline: 1.0976x; 1.0070x over previous
#include <cuda_runtime.h>

#define BB 8
#define PP 12000
#define NP (BB*PP)
#define XN_ 144
#define CELLS (144*144)
#define NBLK 304
#define NWARPS (NBLK*8)

// per-(batch,cell) winning pillar index (last write wins == max p)
__device__ int  g_winner[BB * CELLS];
__device__ int  g_count;
__device__ int2 g_list[NP];      // (pillar id, out-base = b*64*CELLS + flat)

__global__ void k_winner(const int* __restrict__ idx) {
    int i = blockIdx.x * blockDim.x + threadIdx.x;   // grid sized exactly NP
    int y = idx[i * 3 + 1];
    int x = idx[i * 3 + 2];
    x = min(max(x, 0), 143);
    y = min(max(y, 0), 143);
    int b = i / PP;
    int p = i - b * PP;
    atomicMax(&g_winner[b * CELLS + y * XN_ + x], p);
}

// Compact winners into g_list (warp-aggregated atomic: 1 atomicAdd per warp).
__global__ void k_collect(const int* __restrict__ idx) {
    int i = blockIdx.x * blockDim.x + threadIdx.x;
    int lane = threadIdx.x & 31;
    int y = idx[i * 3 + 1];
    int x = idx[i * 3 + 2];
    x = min(max(x, 0), 143);
    y = min(max(y, 0), 143);
    int b = i / PP;
    int p = i - b * PP;
    int flat = y * XN_ + x;
    bool win = (g_winner[b * CELLS + flat] == p);
    unsigned m = __ballot_sync(0xFFFFFFFFu, win);
    int base = 0;
    if (lane == 0 && m) base = atomicAdd(&g_count, __popc(m));
    base = __shfl_sync(0xFFFFFFFFu, base, 0);
    if (win) {
        int pos = base + __popc(m & ((1u << lane) - 1u));
        g_list[pos] = make_int2(i, b * 64 * CELLS + flat);
    }
}

__device__ __forceinline__ unsigned long long fma2(unsigned long long a,
                                                   unsigned long long b,
                                                   unsigned long long c) {
    unsigned long long d;
    asm("fma.rn.f32x2 %0, %1, %2, %3;" : "=l"(d) : "l"(a), "l"(b), "l"(c));
    return d;
}
__device__ __forceinline__ unsigned long long splat2(float s) {
    unsigned long long d;
    asm("mov.b64 %0, {%1, %1};" : "=l"(d) : "f"(s));
    return d;
}
__device__ __forceinline__ unsigned long long pack2(float lo, float hi) {
    unsigned long long d;
    asm("mov.b64 %0, {%1, %2};" : "=l"(d) : "f"(lo), "f"(hi));
    return d;
}
__device__ __forceinline__ void unpack2(unsigned long long v, float& lo, float& hi) {
    asm("mov.b64 {%0, %1}, %2;" : "=f"(lo), "=f"(hi) : "l"(v));
}
__device__ __forceinline__ unsigned smaddr(const void* p) {
    unsigned r;
    asm("{ .reg .u64 t; cvta.to.shared.u64 t, %1; cvt.u32.u64 %0, t; }"
        : "=r"(r) : "l"(p));
    return r;
}
// Copy one 1152-byte pillar global->shared via cp.async (72 x 16B chunks).
__device__ __forceinline__ void cp_pillar(unsigned sbase, const float* g, int lane) {
    asm volatile("cp.async.cg.shared.global [%0], [%1], 16;"
                 :: "r"(sbase + lane * 16), "l"(g + lane * 4));
    asm volatile("cp.async.cg.shared.global [%0], [%1], 16;"
                 :: "r"(sbase + (lane + 32) * 16), "l"(g + (lane + 32) * 4));
    if (lane < 8)
        asm volatile("cp.async.cg.shared.global [%0], [%1], 16;"
                     :: "r"(sbase + (lane + 64) * 16), "l"(g + (lane + 64) * 4));
}

// Persistent kernel over the compacted winner list. One warp per winner.
// Lane = (cg, mg): cg = lane>>2 owns channels [8cg, 8cg+8),
//                  mg = lane&3  owns m-points  [8mg, 8mg+8).
// Pillar data double-buffered in smem via cp.async, prefetched 1 iter ahead;
// list entries prefetched 2 iters ahead.
__global__ void __launch_bounds__(256, 2) k_compute(
    const float* __restrict__ pillars,
    const float* __restrict__ cw,
    const float* __restrict__ gamma,
    const float* __restrict__ beta,
    const float* __restrict__ mean,
    const float* __restrict__ var,
    float* __restrict__ out)
{
    __shared__ __align__(16) float sm[8][2][288];
    const int wlocal = threadIdx.x >> 5;
    const int lane   = threadIdx.x & 31;
    const int cg     = lane >> 2;
    const int mg     = lane & 3;

    // Per-warp constants (loaded once): wp[f][cp] = (w[8cg+2cp][f], w[8cg+2cp+1][f])
    unsigned long long wp[9][4];
    #pragma unroll
    for (int cp = 0; cp < 4; cp++) {
        const float* w0 = cw + (cg * 8 + 2 * cp) * 9;
        #pragma unroll
        for (int f = 0; f < 9; f++)
            wp[f][cp] = pack2(w0[f], w0[9 + f]);
    }
    const int cs = cg * 8 + mg * 2;   // channels this lane stores
    const float s0 = gamma[cs]     * rsqrtf(var[cs]     + 1e-5f);
    const float s1 = gamma[cs + 1] * rsqrtf(var[cs + 1] + 1e-5f);
    const float b0 = beta[cs]     - mean[cs]     * s0;
    const float b1 = beta[cs + 1] - mean[cs + 1] * s1;

    const int count = g_count;
    const int w0id  = (blockIdx.x * blockDim.x + threadIdx.x) >> 5;

    unsigned sbuf0 = smaddr(&sm[wlocal][0][0]);
    unsigned sbuf1 = smaddr(&sm[wlocal][1][0]);

    int i = w0id;
    int2 eA = g_list[(i < count) ? i : 0];
    int2 eB = g_list[(i + NWARPS < count) ? i + NWARPS : 0];
    if (i < count)
        cp_pillar(sbuf0, pillars + (size_t)eA.x * 288, lane);
    asm volatile("cp.async.commit_group;");
    int p = 0;

    for (; i < count; i += NWARPS) {
        // prefetch list entry 2 ahead
        int i2 = i + 2 * NWARPS;
        int2 eC = g_list[(i2 < count) ? i2 : 0];
        // prefetch next pillar into the other buffer
        if (i + NWARPS < count)
            cp_pillar(p ? sbuf0 : sbuf1, pillars + (size_t)eB.x * 288, lane);
        asm volatile("cp.async.commit_group;");
        asm volatile("cp.async.wait_group 1;");   // current buffer ready
        __syncwarp();

        const float* buf = &sm[wlocal][p][0];
        float mx[8];
        #pragma unroll
        for (int j = 0; j < 8; j++) mx[j] = -3.402823466e38f;

        #pragma unroll
        for (int mi = 0; mi < 8; mi++) {
            const float* xr = buf + (mg * 8 + mi) * 9;
            unsigned long long a0 = 0ull, a1 = 0ull, a2 = 0ull, a3 = 0ull;
            #pragma unroll
            for (int f = 0; f < 9; f++) {
                unsigned long long xs = splat2(xr[f]);
                a0 = fma2(xs, wp[f][0], a0);
                a1 = fma2(xs, wp[f][1], a1);
                a2 = fma2(xs, wp[f][2], a2);
                a3 = fma2(xs, wp[f][3], a3);
            }
            float t0, t1;
            unpack2(a0, t0, t1); mx[0] = fmaxf(mx[0], t0); mx[1] = fmaxf(mx[1], t1);
            unpack2(a1, t0, t1); mx[2] = fmaxf(mx[2], t0); mx[3] = fmaxf(mx[3], t1);
            unpack2(a2, t0, t1); mx[4] = fmaxf(mx[4], t0); mx[5] = fmaxf(mx[5], t1);
            unpack2(a3, t0, t1); mx[6] = fmaxf(mx[6], t0); mx[7] = fmaxf(mx[7], t1);
        }
        __syncwarp();   // all lanes done reading buf before it is refilled

        // Reduce max over the 4 mg lanes (lane = cg*4 + mg)
        #pragma unroll
        for (int j = 0; j < 8; j++) {
            mx[j] = fmaxf(mx[j], __shfl_xor_sync(0xFFFFFFFFu, mx[j], 1));
            mx[j] = fmaxf(mx[j], __shfl_xor_sync(0xFFFFFFFFu, mx[j], 2));
        }

        // BN+ReLU applied once to the raw max (scale>0, monotone => exact)
        const float fA = fmaxf(fmaf(mx[mg * 2],     s0, b0), 0.0f);
        const float fB = fmaxf(fmaf(mx[mg * 2 + 1], s1, b1), 0.0f);
        const size_t base = (size_t)eA.y + (size_t)cs * CELLS;
        out[base]         = fA;
        out[base + CELLS] = fB;

        eA = eB; eB = eC; p ^= 1;
    }
}

extern "C" void kernel_launch(void* const* d_in, const int* in_sizes, int n_in,
                              void* d_out, int out_size) {
    const float* pillars = (const float*)d_in[0];
    const int*   idx     = (const int*)d_in[1];
    const float* cw      = (const float*)d_in[2];
    const float* gamma   = (const float*)d_in[3];
    const float* beta    = (const float*)d_in[4];
    const float* mean    = (const float*)d_in[5];
    const float* var     = (const float*)d_in[6];
    float* out = (float*)d_out;

    void *winner_ptr = nullptr, *count_ptr = nullptr;
    cudaGetSymbolAddress(&winner_ptr, g_winner);
    cudaGetSymbolAddress(&count_ptr, g_count);

    cudaMemsetAsync(out, 0, (size_t)out_size * sizeof(float), 0);
    cudaMemsetAsync(winner_ptr, 0xFF, sizeof(int) * BB * CELLS, 0);  // -1
    cudaMemsetAsync(count_ptr, 0, sizeof(int), 0);
    k_winner<<<NP / 256, 256>>>(idx);
    k_collect<<<NP / 256, 256>>>(idx);
    k_compute<<<NBLK, 256>>>(pillars, cw, gamma, beta, mean, var, out);
}